// round 1
// baseline (speedup 1.0000x reference)
#include <cuda_runtime.h>
#include <cstddef>

#define BB   16
#define MID  128
#define OUTC 512
#define HH   112
#define WW   112
#define HW   (HH*WW)      // 12544
#define OH   56
#define OW   56
#define EPSF 1e-5f

// ---- scratch (static device globals; no allocation) ----
__device__ float g_pooled[BB*MID];                       // [b][c]
__device__ float g_gen[BB*MID*9];                        // [b][c*9+tap]
__device__ float g_t[(size_t)BB*MID*HW];                 // global-branch depthwise out
__device__ float g_combined[(size_t)BB*2*MID*HW];        // [b][0..127 local | 128..255 global]

// ============================================================
// 1) global average pool over local half: g_pooled[b][c]
// ============================================================
__global__ void pool_kernel(const float* __restrict__ x) {
    int bc = blockIdx.x;                 // b*MID + c
    int b = bc / MID, c = bc % MID;
    const float4* p = (const float4*)(x + ((size_t)(b*2*MID + c))*HW);
    float s = 0.f;
    for (int i = threadIdx.x; i < HW/4; i += 256) {
        float4 v = p[i];
        s += v.x + v.y + v.z + v.w;
    }
    __shared__ float red[256];
    red[threadIdx.x] = s;
    __syncthreads();
    for (int o = 128; o > 0; o >>= 1) {
        if (threadIdx.x < o) red[threadIdx.x] += red[threadIdx.x + o];
        __syncthreads();
    }
    if (threadIdx.x == 0) g_pooled[bc] = red[0] * (1.f/(float)HW);
}

// ============================================================
// 2) kernel-gen: g_gen[b][o] = relu(sum_c pooled[b,c]*W_kg[o,c])
// ============================================================
__global__ void gen_kernel(const float* __restrict__ Wkg) {
    int b = blockIdx.x;
    int o = blockIdx.y * 128 + threadIdx.x;     // 0..1151
    __shared__ float ps[MID];
    ps[threadIdx.x] = g_pooled[b*MID + threadIdx.x];
    __syncthreads();
    const float4* wr = (const float4*)(Wkg + (size_t)o*MID);
    float s = 0.f;
    #pragma unroll
    for (int i = 0; i < MID/4; i++) {
        float4 w4 = wr[i];
        s += w4.x*ps[4*i] + w4.y*ps[4*i+1] + w4.z*ps[4*i+2] + w4.w*ps[4*i+3];
    }
    g_gen[b*MID*9 + o] = fmaxf(s, 0.f);
}

// ============================================================
// 3) depthwise 3x3 (templated dilation; pad == dil).
//    Whole plane staged in smem with zero halo -> 9 LDS / output.
//    kper==nullptr => per-sample kernels from g_gen (local branch)
// ============================================================
template<int DIL>
__global__ void dw_kernel(const float* __restrict__ x, int in_chan_off,
                          const float* __restrict__ kper,
                          const float* __restrict__ bias,
                          float* __restrict__ outbuf, int out_nchan) {
    constexpr int P  = DIL;
    constexpr int W2 = WW + 2*P;
    constexpr int H2 = HH + 2*P;
    extern __shared__ float sm[];     // H2*W2 floats
    int bc = blockIdx.x;
    int b = bc / MID, c = bc % MID;
    const float* in = x + ((size_t)(b*2*MID) + in_chan_off + c)*HW;

    for (int i = threadIdx.x; i < H2*W2; i += 256) sm[i] = 0.f;
    __syncthreads();
    for (int i = threadIdx.x; i < HW; i += 256) {
        int h = i / WW, w = i % WW;
        sm[(h+P)*W2 + w + P] = in[i];
    }
    __syncthreads();

    float k[9];
    const float* kp = kper ? (kper + c*9) : (g_gen + (b*MID + c)*9);
    #pragma unroll
    for (int t = 0; t < 9; t++) k[t] = kp[t];
    float bv = bias ? bias[c] : 0.f;

    float* out = outbuf + ((size_t)b*out_nchan + c)*HW;
    for (int i = threadIdx.x; i < HW; i += 256) {
        int h = i / WW, w = i % WW;
        const float* base = sm + h*W2 + w;
        float s = bv;
        #pragma unroll
        for (int kh = 0; kh < 3; kh++)
            #pragma unroll
            for (int kw = 0; kw < 3; kw++)
                s = fmaf(base[kh*DIL*W2 + kw*DIL], k[kh*3+kw], s);
        out[i] = s;
    }
}

// ============================================================
// 4) 1x1 conv (128->128) + bias + BN + ReLU, writes combined[128..255]
//    GEMM per image: 128co x 128px tiles, 256 thr, 8x8 reg tile
// ============================================================
__global__ void pw_kernel(const float* __restrict__ wpw, const float* __restrict__ bpw,
                          const float* __restrict__ bn_g, const float* __restrict__ bn_b,
                          const float* __restrict__ bn_m, const float* __restrict__ bn_v) {
    __shared__ float wS[16*132];
    __shared__ float tS[16*132];
    int b  = blockIdx.y;
    int p0 = blockIdx.x * 128;
    int tid = threadIdx.x;
    int ty = tid >> 4, tx = tid & 15;
    float acc[8][8] = {};              // [co][px]
    const float* tbase = g_t + (size_t)b*MID*HW;

    for (int kc = 0; kc < 8; kc++) {
        __syncthreads();
        for (int idx = tid; idx < 2048; idx += 256) {   // wS[k][co]
            int k = idx & 15, co = idx >> 4;
            wS[k*132 + co] = wpw[co*MID + kc*16 + k];
        }
        for (int idx = tid; idx < 2048; idx += 256) {   // tS[k][px]
            int k = idx >> 7, px = idx & 127;
            tS[k*132 + px] = tbase[(kc*16 + k)*HW + p0 + px];
        }
        __syncthreads();
        #pragma unroll
        for (int k = 0; k < 16; k++) {
            float4 a0 = *(const float4*)&wS[k*132 + ty*8];
            float4 a1 = *(const float4*)&wS[k*132 + ty*8 + 4];
            float4 b0 = *(const float4*)&tS[k*132 + tx*8];
            float4 b1 = *(const float4*)&tS[k*132 + tx*8 + 4];
            float a[8] = {a0.x,a0.y,a0.z,a0.w,a1.x,a1.y,a1.z,a1.w};
            float bb[8] = {b0.x,b0.y,b0.z,b0.w,b1.x,b1.y,b1.z,b1.w};
            #pragma unroll
            for (int i = 0; i < 8; i++)
                #pragma unroll
                for (int j = 0; j < 8; j++)
                    acc[i][j] = fmaf(a[i], bb[j], acc[i][j]);
        }
    }
    #pragma unroll
    for (int i = 0; i < 8; i++) {
        int co = ty*8 + i;
        float inv = bn_g[co] * rsqrtf(bn_v[co] + EPSF);
        float sh  = bn_b[co] - bn_m[co]*inv + bpw[co]*inv;
        float* o = g_combined + ((size_t)(b*2*MID) + MID + co)*HW + p0;
        #pragma unroll
        for (int j = 0; j < 8; j++)
            o[tx*8 + j] = fmaxf(fmaf(acc[i][j], inv, sh), 0.f);
    }
}

// ============================================================
// 5) downsample 3x3 s2 p1 (256->512) + bias + BN + ReLU
//    tile: 8oh x 8ow x 128co, 128 threads, 8px x 8co per thread
// ============================================================
__global__ void __launch_bounds__(128) ds_kernel(
    const float* __restrict__ dsw, const float* __restrict__ dsb,
    const float* __restrict__ bn_g, const float* __restrict__ bn_b,
    const float* __restrict__ bn_m, const float* __restrict__ bn_v,
    float* __restrict__ out) {
    __shared__ float wS[8*9*128];     // [cin][tap][co]
    __shared__ float pS[8*289];       // [cin][17*17]
    int b   = blockIdx.z;
    int coB = blockIdx.y * 128;
    int tY  = blockIdx.x / 7, tX = blockIdx.x % 7;
    int oh0 = tY*8, ow0 = tX*8;
    int ih0 = oh0*2 - 1, iw0 = ow0*2 - 1;
    int tid = threadIdx.x;
    int pxg = tid >> 4;               // output row within tile (0..7)
    int cog = tid & 15;               // co group of 8 (0..15)
    float acc[8][8] = {};             // [co][ow]
    const float* cbase = g_combined + (size_t)b*2*MID*HW;

    for (int chunk = 0; chunk < 32; chunk++) {
        int cin0 = chunk*8;
        __syncthreads();
        {   // weights: thread=co, 72 contiguous floats = 18 float4
            int co = tid;
            const float4* src = (const float4*)(dsw + ((size_t)(coB+co))*2304 + cin0*9);
            #pragma unroll
            for (int v = 0; v < 18; v++) {
                float4 f = src[v];
                int r = v*4;
                wS[(r+0)*128 + co] = f.x;
                wS[(r+1)*128 + co] = f.y;
                wS[(r+2)*128 + co] = f.z;
                wS[(r+3)*128 + co] = f.w;
            }
        }
        for (int idx = tid; idx < 8*289; idx += 128) {
            int cin = idx / 289, r = idx % 289;
            int rr = r / 17, cc = r % 17;
            int ih = ih0 + rr, iw = iw0 + cc;
            float v = 0.f;
            if ((unsigned)ih < HH && (unsigned)iw < WW)
                v = cbase[((size_t)(cin0+cin))*HW + ih*WW + iw];
            pS[idx] = v;
        }
        __syncthreads();
        #pragma unroll
        for (int cin = 0; cin < 8; cin++) {
            #pragma unroll
            for (int kh = 0; kh < 3; kh++) {
                const float* prow = &pS[cin*289 + (2*pxg + kh)*17];
                #pragma unroll
                for (int kw = 0; kw < 3; kw++) {
                    const float* wp = &wS[(cin*9 + kh*3 + kw)*128 + cog*8];
                    float4 wa = *(const float4*)wp;
                    float4 wb = *(const float4*)(wp + 4);
                    float w0[8] = {wa.x,wa.y,wa.z,wa.w,wb.x,wb.y,wb.z,wb.w};
                    float p[8];
                    #pragma unroll
                    for (int j = 0; j < 8; j++) p[j] = prow[2*j + kw];
                    #pragma unroll
                    for (int i = 0; i < 8; i++)
                        #pragma unroll
                        for (int j = 0; j < 8; j++)
                            acc[i][j] = fmaf(w0[i], p[j], acc[i][j]);
                }
            }
        }
    }
    int oh = oh0 + pxg;
    #pragma unroll
    for (int i = 0; i < 8; i++) {
        int co = coB + cog*8 + i;
        float inv = bn_g[co] * rsqrtf(bn_v[co] + EPSF);
        float sh  = bn_b[co] - bn_m[co]*inv + dsb[co]*inv;
        float* op = out + ((size_t)(b*OUTC + co)*OH + oh)*OW + ow0;
        #pragma unroll
        for (int j = 0; j < 8; j++)
            op[j] = fmaxf(fmaf(acc[i][j], inv, sh), 0.f);
    }
}

// ============================================================
extern "C" void kernel_launch(void* const* d_in, const int* in_sizes, int n_in,
                              void* d_out, int out_size) {
    const float* x     = (const float*)d_in[0];
    const float* Wkg   = (const float*)d_in[1];
    const float* gdw_w = (const float*)d_in[2];
    const float* gdw_b = (const float*)d_in[3];
    const float* gpw_w = (const float*)d_in[4];
    const float* gpw_b = (const float*)d_in[5];
    const float* bn1_g = (const float*)d_in[6];
    const float* bn1_b = (const float*)d_in[7];
    const float* bn1_m = (const float*)d_in[8];
    const float* bn1_v = (const float*)d_in[9];
    const float* ds_w  = (const float*)d_in[10];
    const float* ds_b  = (const float*)d_in[11];
    const float* bn2_g = (const float*)d_in[12];
    const float* bn2_b = (const float*)d_in[13];
    const float* bn2_m = (const float*)d_in[14];
    const float* bn2_v = (const float*)d_in[15];
    float* out = (float*)d_out;

    // dynamic smem sizes for full-plane depthwise staging
    const int smem1 = (HH+2)*(WW+2)*sizeof(float);   // 51984 B
    const int smem2 = (HH+4)*(WW+4)*sizeof(float);   // 53824 B
    cudaFuncSetAttribute(dw_kernel<1>, cudaFuncAttributeMaxDynamicSharedMemorySize, smem1);
    cudaFuncSetAttribute(dw_kernel<2>, cudaFuncAttributeMaxDynamicSharedMemorySize, smem2);

    // resolve scratch pointers
    float* t_ptr;       cudaGetSymbolAddress((void**)&t_ptr, g_t);
    float* comb_ptr;    cudaGetSymbolAddress((void**)&comb_ptr, g_combined);

    pool_kernel<<<BB*MID, 256>>>(x);
    gen_kernel<<<dim3(BB, 9), 128>>>(Wkg);
    // local branch: per-sample depthwise -> combined[0..127]
    dw_kernel<1><<<BB*MID, 256, smem1>>>(x, 0, nullptr, nullptr, comb_ptr, 2*MID);
    // global branch: dilated depthwise -> g_t
    dw_kernel<2><<<BB*MID, 256, smem2>>>(x, MID, gdw_w, gdw_b, t_ptr, MID);
    // 1x1 + BN + ReLU -> combined[128..255]
    pw_kernel<<<dim3(HW/128, BB), 256>>>(gpw_w, gpw_b, bn1_g, bn1_b, bn1_m, bn1_v);
    // downsample + BN + ReLU -> out
    ds_kernel<<<dim3(49, 4, BB), 128>>>(ds_w, ds_b, bn2_g, bn2_b, bn2_m, bn2_v, out);
}

// round 3
// speedup vs baseline: 1.3215x; 1.3215x over previous
#include <cuda_runtime.h>
#include <cstddef>
#include <cstdint>

#define BB   16
#define MID  128
#define OUTC 512
#define HH   112
#define WW   112
#define HW   (HH*WW)      // 12544
#define OH   56
#define OW   56
#define EPSF 1e-5f

// ---- packed f32x2 helpers (Blackwell sm_103a) ----
#define FMA2(acc, a, b) \
    asm("fma.rn.f32x2 %0, %1, %2, %0;" : "+l"(acc) : "l"(a), "l"(b))
#define PACK2(out, lo, hi) \
    asm("mov.b64 %0, {%1, %2};" : "=l"(out) : "r"(lo), "r"(hi))
#define UNPACK2(lo, hi, v) \
    asm("mov.b64 {%0, %1}, %2;" : "=r"(lo), "=r"(hi) : "l"(v))

// ---- scratch (static device globals; no allocation) ----
__device__ float g_pooled[BB*MID];                       // [b][c]
__device__ float g_gen[BB*MID*9];                        // [b][c*9+tap]
__device__ float g_t[(size_t)BB*MID*HW];                 // global-branch depthwise out
__device__ float g_combined[(size_t)BB*2*MID*HW];        // [b][0..127 local | 128..255 global]

// ============================================================
// 1) global average pool over local half: g_pooled[b][c]
// ============================================================
__global__ void pool_kernel(const float* __restrict__ x) {
    int bc = blockIdx.x;                 // b*MID + c
    int b = bc / MID, c = bc % MID;
    const float4* p = (const float4*)(x + ((size_t)(b*2*MID + c))*HW);
    float s = 0.f;
    for (int i = threadIdx.x; i < HW/4; i += 256) {
        float4 v = p[i];
        s += v.x + v.y + v.z + v.w;
    }
    __shared__ float red[256];
    red[threadIdx.x] = s;
    __syncthreads();
    for (int o = 128; o > 0; o >>= 1) {
        if (threadIdx.x < o) red[threadIdx.x] += red[threadIdx.x + o];
        __syncthreads();
    }
    if (threadIdx.x == 0) g_pooled[bc] = red[0] * (1.f/(float)HW);
}

// ============================================================
// 2) kernel-gen: g_gen[b][o] = relu(sum_c pooled[b,c]*W_kg[o,c])
// ============================================================
__global__ void gen_kernel(const float* __restrict__ Wkg) {
    int b = blockIdx.x;
    int o = blockIdx.y * 128 + threadIdx.x;     // 0..1151
    __shared__ float ps[MID];
    ps[threadIdx.x] = g_pooled[b*MID + threadIdx.x];
    __syncthreads();
    const float4* wr = (const float4*)(Wkg + (size_t)o*MID);
    float s = 0.f;
    #pragma unroll
    for (int i = 0; i < MID/4; i++) {
        float4 w4 = wr[i];
        s += w4.x*ps[4*i] + w4.y*ps[4*i+1] + w4.z*ps[4*i+2] + w4.w*ps[4*i+3];
    }
    g_gen[b*MID*9 + o] = fmaxf(s, 0.f);
}

// ============================================================
// 3) depthwise 3x3 (templated dilation; pad == dil).
// ============================================================
template<int DIL>
__global__ void dw_kernel(const float* __restrict__ x, int in_chan_off,
                          const float* __restrict__ kper,
                          const float* __restrict__ bias,
                          float* __restrict__ outbuf, int out_nchan) {
    constexpr int P  = DIL;
    constexpr int W2 = WW + 2*P;
    constexpr int H2 = HH + 2*P;
    extern __shared__ float sm[];     // H2*W2 floats
    int bc = blockIdx.x;
    int b = bc / MID, c = bc % MID;
    const float* in = x + ((size_t)(b*2*MID) + in_chan_off + c)*HW;

    for (int i = threadIdx.x; i < H2*W2; i += 256) sm[i] = 0.f;
    __syncthreads();
    for (int i = threadIdx.x; i < HW; i += 256) {
        int h = i / WW, w = i % WW;
        sm[(h+P)*W2 + w + P] = in[i];
    }
    __syncthreads();

    float k[9];
    const float* kp = kper ? (kper + c*9) : (g_gen + (b*MID + c)*9);
    #pragma unroll
    for (int t = 0; t < 9; t++) k[t] = kp[t];
    float bv = bias ? bias[c] : 0.f;

    float* out = outbuf + ((size_t)b*out_nchan + c)*HW;
    for (int i = threadIdx.x; i < HW; i += 256) {
        int h = i / WW, w = i % WW;
        const float* base = sm + h*W2 + w;
        float s = bv;
        #pragma unroll
        for (int kh = 0; kh < 3; kh++)
            #pragma unroll
            for (int kw = 0; kw < 3; kw++)
                s = fmaf(base[kh*DIL*W2 + kw*DIL], k[kh*3+kw], s);
        out[i] = s;
    }
}

// ============================================================
// 4) 1x1 conv (128->128) + bias + BN + ReLU  (f32x2 packed FMA)
//    GEMM per image: 128co x 128px tiles, 256 thr, 8co x 8px reg tile
//    acc paired over px (pairs come free from contiguous smem)
// ============================================================
__global__ void pw_kernel(const float* __restrict__ wpw, const float* __restrict__ bpw,
                          const float* __restrict__ bn_g, const float* __restrict__ bn_b,
                          const float* __restrict__ bn_m, const float* __restrict__ bn_v) {
    __shared__ __align__(16) float wS[16*132];
    __shared__ __align__(16) float tS[16*132];
    int b  = blockIdx.y;
    int p0 = blockIdx.x * 128;
    int tid = threadIdx.x;
    int ty = tid >> 4, tx = tid & 15;
    unsigned long long acc[8][4];              // [co][px-pair]
    #pragma unroll
    for (int i = 0; i < 8; i++)
        #pragma unroll
        for (int j = 0; j < 4; j++) acc[i][j] = 0ULL;
    const float* tbase = g_t + (size_t)b*MID*HW;

    for (int kc = 0; kc < 8; kc++) {
        __syncthreads();
        for (int idx = tid; idx < 2048; idx += 256) {   // wS[k][co]
            int k = idx & 15, co = idx >> 4;
            wS[k*132 + co] = wpw[co*MID + kc*16 + k];
        }
        for (int idx = tid; idx < 2048; idx += 256) {   // tS[k][px]
            int k = idx >> 7, px = idx & 127;
            tS[k*132 + px] = tbase[(kc*16 + k)*HW + p0 + px];
        }
        __syncthreads();
        #pragma unroll
        for (int k = 0; k < 16; k++) {
            float4 a0 = *(const float4*)&wS[k*132 + ty*8];
            float4 a1 = *(const float4*)&wS[k*132 + ty*8 + 4];
            float a[8] = {a0.x,a0.y,a0.z,a0.w,a1.x,a1.y,a1.z,a1.w};
            unsigned long long ad[8];
            #pragma unroll
            for (int i = 0; i < 8; i++) {
                unsigned int ab = __float_as_uint(a[i]);
                PACK2(ad[i], ab, ab);
            }
            const ulonglong2* bp = (const ulonglong2*)&tS[k*132 + tx*8];
            ulonglong2 b01 = bp[0];   // (px0,px1),(px2,px3)
            ulonglong2 b23 = bp[1];   // (px4,px5),(px6,px7)
            unsigned long long bv[4] = {b01.x, b01.y, b23.x, b23.y};
            #pragma unroll
            for (int i = 0; i < 8; i++)
                #pragma unroll
                for (int j = 0; j < 4; j++)
                    FMA2(acc[i][j], ad[i], bv[j]);
        }
    }
    #pragma unroll
    for (int i = 0; i < 8; i++) {
        int co = ty*8 + i;
        float inv = bn_g[co] * rsqrtf(bn_v[co] + EPSF);
        float sh  = bn_b[co] - bn_m[co]*inv + bpw[co]*inv;
        float* o = g_combined + ((size_t)(b*2*MID) + MID + co)*HW + p0 + tx*8;
        #pragma unroll
        for (int j = 0; j < 4; j++) {
            unsigned int lo, hi;
            UNPACK2(lo, hi, acc[i][j]);
            o[2*j]   = fmaxf(fmaf(__uint_as_float(lo), inv, sh), 0.f);
            o[2*j+1] = fmaxf(fmaf(__uint_as_float(hi), inv, sh), 0.f);
        }
    }
}

// ============================================================
// 5) downsample 3x3 s2 p1 (256->512) + bias + BN + ReLU  (f32x2)
//    tile: 8oh x 8ow x 128co, 128 threads, 8px x 8co per thread
//    acc paired over co (pairs come free from LDS.128 of wS)
// ============================================================
__global__ void __launch_bounds__(128) ds_kernel(
    const float* __restrict__ dsw, const float* __restrict__ dsb,
    const float* __restrict__ bn_g, const float* __restrict__ bn_b,
    const float* __restrict__ bn_m, const float* __restrict__ bn_v,
    float* __restrict__ out) {
    __shared__ __align__(16) float wS[8*9*128];     // [cin][tap][co]
    __shared__ __align__(16) float pS[8*289];       // [cin][17*17]
    int b   = blockIdx.z;
    int coB = blockIdx.y * 128;
    int tY  = blockIdx.x / 7, tX = blockIdx.x % 7;
    int oh0 = tY*8, ow0 = tX*8;
    int ih0 = oh0*2 - 1, iw0 = ow0*2 - 1;
    int tid = threadIdx.x;
    int pxg = tid >> 4;               // output row within tile (0..7)
    int cog = tid & 15;               // co group of 8 (0..15)
    unsigned long long acc[4][8];     // [co-pair][ow]
    #pragma unroll
    for (int i = 0; i < 4; i++)
        #pragma unroll
        for (int j = 0; j < 8; j++) acc[i][j] = 0ULL;
    const float* cbase = g_combined + (size_t)b*2*MID*HW;

    for (int chunk = 0; chunk < 32; chunk++) {
        int cin0 = chunk*8;
        __syncthreads();
        {   // weights: thread=co, 72 contiguous floats = 18 float4
            int co = tid;
            const float4* src = (const float4*)(dsw + ((size_t)(coB+co))*2304 + cin0*9);
            #pragma unroll
            for (int v = 0; v < 18; v++) {
                float4 f = src[v];
                int r = v*4;
                wS[(r+0)*128 + co] = f.x;
                wS[(r+1)*128 + co] = f.y;
                wS[(r+2)*128 + co] = f.z;
                wS[(r+3)*128 + co] = f.w;
            }
        }
        for (int idx = tid; idx < 8*289; idx += 128) {
            int cin = idx / 289, r = idx % 289;
            int rr = r / 17, cc = r % 17;
            int ih = ih0 + rr, iw = iw0 + cc;
            float v = 0.f;
            if ((unsigned)ih < HH && (unsigned)iw < WW)
                v = cbase[((size_t)(cin0+cin))*HW + ih*WW + iw];
            pS[idx] = v;
        }
        __syncthreads();
        #pragma unroll
        for (int cin = 0; cin < 8; cin++) {
            #pragma unroll
            for (int kh = 0; kh < 3; kh++) {
                const float* prow = &pS[cin*289 + (2*pxg + kh)*17];
                #pragma unroll
                for (int kw = 0; kw < 3; kw++) {
                    const ulonglong2* wp =
                        (const ulonglong2*)&wS[(cin*9 + kh*3 + kw)*128 + cog*8];
                    ulonglong2 wA = wp[0];            // (w0,w1),(w2,w3)
                    ulonglong2 wB = wp[1];            // (w4,w5),(w6,w7)
                    unsigned long long wv[4] = {wA.x, wA.y, wB.x, wB.y};
                    unsigned long long pd[8];
                    #pragma unroll
                    for (int j = 0; j < 8; j++) {
                        unsigned int pb = __float_as_uint(prow[2*j + kw]);
                        PACK2(pd[j], pb, pb);
                    }
                    #pragma unroll
                    for (int i = 0; i < 4; i++)
                        #pragma unroll
                        for (int j = 0; j < 8; j++)
                            FMA2(acc[i][j], wv[i], pd[j]);
                }
            }
        }
    }
    int oh = oh0 + pxg;
    #pragma unroll
    for (int i = 0; i < 4; i++) {
        int co0 = coB + cog*8 + 2*i;
        float inv0 = bn_g[co0]   * rsqrtf(bn_v[co0]   + EPSF);
        float sh0  = bn_b[co0]   - bn_m[co0]*inv0   + dsb[co0]*inv0;
        float inv1 = bn_g[co0+1] * rsqrtf(bn_v[co0+1] + EPSF);
        float sh1  = bn_b[co0+1] - bn_m[co0+1]*inv1 + dsb[co0+1]*inv1;
        float* op0 = out + ((size_t)(b*OUTC + co0  )*OH + oh)*OW + ow0;
        float* op1 = out + ((size_t)(b*OUTC + co0+1)*OH + oh)*OW + ow0;
        #pragma unroll
        for (int j = 0; j < 8; j++) {
            unsigned int lo, hi;
            UNPACK2(lo, hi, acc[i][j]);
            op0[j] = fmaxf(fmaf(__uint_as_float(lo), inv0, sh0), 0.f);
            op1[j] = fmaxf(fmaf(__uint_as_float(hi), inv1, sh1), 0.f);
        }
    }
}

// ============================================================
extern "C" void kernel_launch(void* const* d_in, const int* in_sizes, int n_in,
                              void* d_out, int out_size) {
    const float* x     = (const float*)d_in[0];
    const float* Wkg   = (const float*)d_in[1];
    const float* gdw_w = (const float*)d_in[2];
    const float* gdw_b = (const float*)d_in[3];
    const float* gpw_w = (const float*)d_in[4];
    const float* gpw_b = (const float*)d_in[5];
    const float* bn1_g = (const float*)d_in[6];
    const float* bn1_b = (const float*)d_in[7];
    const float* bn1_m = (const float*)d_in[8];
    const float* bn1_v = (const float*)d_in[9];
    const float* ds_w  = (const float*)d_in[10];
    const float* ds_b  = (const float*)d_in[11];
    const float* bn2_g = (const float*)d_in[12];
    const float* bn2_b = (const float*)d_in[13];
    const float* bn2_m = (const float*)d_in[14];
    const float* bn2_v = (const float*)d_in[15];
    float* out = (float*)d_out;

    const int smem1 = (HH+2)*(WW+2)*sizeof(float);   // 51984 B
    const int smem2 = (HH+4)*(WW+4)*sizeof(float);   // 53824 B
    cudaFuncSetAttribute(dw_kernel<1>, cudaFuncAttributeMaxDynamicSharedMemorySize, smem1);
    cudaFuncSetAttribute(dw_kernel<2>, cudaFuncAttributeMaxDynamicSharedMemorySize, smem2);

    float* t_ptr;       cudaGetSymbolAddress((void**)&t_ptr, g_t);
    float* comb_ptr;    cudaGetSymbolAddress((void**)&comb_ptr, g_combined);

    pool_kernel<<<BB*MID, 256>>>(x);
    gen_kernel<<<dim3(BB, 9), 128>>>(Wkg);
    dw_kernel<1><<<BB*MID, 256, smem1>>>(x, 0, nullptr, nullptr, comb_ptr, 2*MID);
    dw_kernel<2><<<BB*MID, 256, smem2>>>(x, MID, gdw_w, gdw_b, t_ptr, MID);
    pw_kernel<<<dim3(HW/128, BB), 256>>>(gpw_w, gpw_b, bn1_g, bn1_b, bn1_m, bn1_v);
    ds_kernel<<<dim3(49, 4, BB), 128>>>(ds_w, ds_b, bn2_g, bn2_b, bn2_m, bn2_v, out);
}

// round 6
// speedup vs baseline: 2.1362x; 1.6165x over previous
#include <cuda_runtime.h>
#include <cuda_bf16.h>
#include <cstddef>
#include <cstdint>

#define BB   16
#define MID  128
#define OUTC 512
#define HH   112
#define WW   112
#define HW   (HH*WW)      // 12544
#define OH   56
#define OW   56
#define OHW  (OH*OW)      // 3136
#define EPSF 1e-5f

// ---- packed f32x2 helpers ----
#define FMA2(acc, a, b) \
    asm("fma.rn.f32x2 %0, %1, %2, %0;" : "+l"(acc) : "l"(a), "l"(b))
#define PACK2(out, lo, hi) \
    asm("mov.b64 %0, {%1, %2};" : "=l"(out) : "r"(lo), "r"(hi))
#define UNPACK2(lo, hi, v) \
    asm("mov.b64 {%0, %1}, %2;" : "=r"(lo), "=r"(hi) : "l"(v))

// ---- legacy tensor-core mma (baseline PTX, works on sm_103 non-'a') ----
__device__ __forceinline__ void mma_bf16(float* c, const uint32_t* a,
                                         uint32_t b0, uint32_t b1) {
    asm volatile(
        "mma.sync.aligned.m16n8k16.row.col.f32.bf16.bf16.f32 "
        "{%0,%1,%2,%3}, {%4,%5,%6,%7}, {%8,%9}, {%0,%1,%2,%3};"
        : "+f"(c[0]), "+f"(c[1]), "+f"(c[2]), "+f"(c[3])
        : "r"(a[0]), "r"(a[1]), "r"(a[2]), "r"(a[3]), "r"(b0), "r"(b1));
}

// ---- scratch (static device globals; no allocation) ----
__device__ float g_pooled[BB*MID];
__device__ float g_gen[BB*MID*9];
__device__ float g_t[(size_t)BB*MID*HW];
__device__ float g_combined[(size_t)BB*2*MID*HW];                 // NCHW fp32
__device__ __nv_bfloat16 g_bhi[(size_t)BB*114*114*256];           // padded NHWC hi
__device__ __nv_bfloat16 g_blo[(size_t)BB*114*114*256];           // padded NHWC lo
__device__ __nv_bfloat16 g_whi[(size_t)9*OUTC*256];               // [tap][co][cin] hi
__device__ __nv_bfloat16 g_wlo[(size_t)9*OUTC*256];               // [tap][co][cin] lo

// ============================================================
// 1) global average pool
// ============================================================
__global__ void pool_kernel(const float* __restrict__ x) {
    int bc = blockIdx.x;
    int b = bc / MID, c = bc % MID;
    const float4* p = (const float4*)(x + ((size_t)(b*2*MID + c))*HW);
    float s = 0.f;
    for (int i = threadIdx.x; i < HW/4; i += 256) {
        float4 v = p[i];
        s += v.x + v.y + v.z + v.w;
    }
    __shared__ float red[256];
    red[threadIdx.x] = s;
    __syncthreads();
    for (int o = 128; o > 0; o >>= 1) {
        if (threadIdx.x < o) red[threadIdx.x] += red[threadIdx.x + o];
        __syncthreads();
    }
    if (threadIdx.x == 0) g_pooled[bc] = red[0] * (1.f/(float)HW);
}

// ============================================================
// 2) kernel-gen
// ============================================================
__global__ void gen_kernel(const float* __restrict__ Wkg) {
    int b = blockIdx.x;
    int o = blockIdx.y * 128 + threadIdx.x;
    __shared__ float ps[MID];
    ps[threadIdx.x] = g_pooled[b*MID + threadIdx.x];
    __syncthreads();
    const float4* wr = (const float4*)(Wkg + (size_t)o*MID);
    float s = 0.f;
    #pragma unroll
    for (int i = 0; i < MID/4; i++) {
        float4 w4 = wr[i];
        s += w4.x*ps[4*i] + w4.y*ps[4*i+1] + w4.z*ps[4*i+2] + w4.w*ps[4*i+3];
    }
    g_gen[b*MID*9 + o] = fmaxf(s, 0.f);
}

// ============================================================
// 3) depthwise 3x3 (dil 1 or 2)
// ============================================================
template<int DIL>
__global__ void dw_kernel(const float* __restrict__ x, int in_chan_off,
                          const float* __restrict__ kper,
                          const float* __restrict__ bias,
                          float* __restrict__ outbuf, int out_nchan) {
    constexpr int P  = DIL;
    constexpr int W2 = WW + 2*P;
    constexpr int H2 = HH + 2*P;
    extern __shared__ float sm[];
    int bc = blockIdx.x;
    int b = bc / MID, c = bc % MID;
    const float* in = x + ((size_t)(b*2*MID) + in_chan_off + c)*HW;

    for (int i = threadIdx.x; i < H2*W2; i += 256) sm[i] = 0.f;
    __syncthreads();
    for (int i = threadIdx.x; i < HW; i += 256) {
        int h = i / WW, w = i % WW;
        sm[(h+P)*W2 + w + P] = in[i];
    }
    __syncthreads();

    float k[9];
    const float* kp = kper ? (kper + c*9) : (g_gen + (b*MID + c)*9);
    #pragma unroll
    for (int t = 0; t < 9; t++) k[t] = kp[t];
    float bv = bias ? bias[c] : 0.f;

    float* out = outbuf + ((size_t)b*out_nchan + c)*HW;
    for (int i = threadIdx.x; i < HW; i += 256) {
        int h = i / WW, w = i % WW;
        const float* base = sm + h*W2 + w;
        float s = bv;
        #pragma unroll
        for (int kh = 0; kh < 3; kh++)
            #pragma unroll
            for (int kw = 0; kw < 3; kw++)
                s = fmaf(base[kh*DIL*W2 + kw*DIL], k[kh*3+kw], s);
        out[i] = s;
    }
}

// ============================================================
// 4) 1x1 conv + bias + BN + ReLU (f32x2)
// ============================================================
__global__ void pw_kernel(const float* __restrict__ wpw, const float* __restrict__ bpw,
                          const float* __restrict__ bn_g, const float* __restrict__ bn_b,
                          const float* __restrict__ bn_m, const float* __restrict__ bn_v) {
    __shared__ __align__(16) float wS[16*132];
    __shared__ __align__(16) float tS[16*132];
    int b  = blockIdx.y;
    int p0 = blockIdx.x * 128;
    int tid = threadIdx.x;
    int ty = tid >> 4, tx = tid & 15;
    unsigned long long acc[8][4];
    #pragma unroll
    for (int i = 0; i < 8; i++)
        #pragma unroll
        for (int j = 0; j < 4; j++) acc[i][j] = 0ULL;
    const float* tbase = g_t + (size_t)b*MID*HW;

    for (int kc = 0; kc < 8; kc++) {
        __syncthreads();
        for (int idx = tid; idx < 2048; idx += 256) {
            int k = idx & 15, co = idx >> 4;
            wS[k*132 + co] = wpw[co*MID + kc*16 + k];
        }
        for (int idx = tid; idx < 2048; idx += 256) {
            int k = idx >> 7, px = idx & 127;
            tS[k*132 + px] = tbase[(kc*16 + k)*HW + p0 + px];
        }
        __syncthreads();
        #pragma unroll
        for (int k = 0; k < 16; k++) {
            float4 a0 = *(const float4*)&wS[k*132 + ty*8];
            float4 a1 = *(const float4*)&wS[k*132 + ty*8 + 4];
            float a[8] = {a0.x,a0.y,a0.z,a0.w,a1.x,a1.y,a1.z,a1.w};
            unsigned long long ad[8];
            #pragma unroll
            for (int i = 0; i < 8; i++) {
                unsigned int ab = __float_as_uint(a[i]);
                PACK2(ad[i], ab, ab);
            }
            const ulonglong2* bp = (const ulonglong2*)&tS[k*132 + tx*8];
            ulonglong2 b01 = bp[0];
            ulonglong2 b23 = bp[1];
            unsigned long long bv[4] = {b01.x, b01.y, b23.x, b23.y};
            #pragma unroll
            for (int i = 0; i < 8; i++)
                #pragma unroll
                for (int j = 0; j < 4; j++)
                    FMA2(acc[i][j], ad[i], bv[j]);
        }
    }
    #pragma unroll
    for (int i = 0; i < 8; i++) {
        int co = ty*8 + i;
        float inv = bn_g[co] * rsqrtf(bn_v[co] + EPSF);
        float sh  = bn_b[co] - bn_m[co]*inv + bpw[co]*inv;
        float* o = g_combined + ((size_t)(b*2*MID) + MID + co)*HW + p0 + tx*8;
        #pragma unroll
        for (int j = 0; j < 4; j++) {
            unsigned int lo, hi;
            UNPACK2(lo, hi, acc[i][j]);
            o[2*j]   = fmaxf(fmaf(__uint_as_float(lo), inv, sh), 0.f);
            o[2*j+1] = fmaxf(fmaf(__uint_as_float(hi), inv, sh), 0.f);
        }
    }
}

// ============================================================
// 5a) weight repack: dsw[co][cin][tap] -> [tap][co][cin] bf16 hi/lo
// ============================================================
__global__ void repack_kernel(const float* __restrict__ dsw) {
    int co = blockIdx.x, cin = threadIdx.x;
    const float* src = dsw + ((size_t)co*256 + cin)*9;
    #pragma unroll
    for (int t = 0; t < 9; t++) {
        float v = src[t];
        __nv_bfloat16 h = __float2bfloat16(v);
        float r = v - __bfloat162float(h);
        size_t idx = ((size_t)t*OUTC + co)*256 + cin;
        g_whi[idx] = h;
        g_wlo[idx] = __float2bfloat16(r);
    }
}

// ============================================================
// 5b) border zero for padded NHWC bf16 buffers
// ============================================================
__global__ void border_kernel() {
    size_t base = (size_t)blockIdx.x * 114*114*256;
    int tid = threadIdx.x;
    __nv_bfloat16 z = __float2bfloat16(0.f);
    for (int idx = tid; idx < 114*256; idx += 256) {
        g_bhi[base + idx] = z;  g_blo[base + idx] = z;
        g_bhi[base + (size_t)113*114*256 + idx] = z;
        g_blo[base + (size_t)113*114*256 + idx] = z;
    }
    for (int idx = tid; idx < 112*256; idx += 256) {
        int h = idx >> 8, c = idx & 255;
        size_t i0 = base + ((size_t)(h+1)*114)*256 + c;
        size_t i1 = base + ((size_t)(h+1)*114 + 113)*256 + c;
        g_bhi[i0] = z; g_blo[i0] = z;
        g_bhi[i1] = z; g_blo[i1] = z;
    }
}

// ============================================================
// 5c) transpose NCHW fp32 -> padded NHWC bf16 hi/lo
// ============================================================
__global__ void transpose_kernel() {
    __shared__ float t[64][113];
    int h = blockIdx.x, b = blockIdx.y;
    int tid = threadIdx.x;
    for (int c0 = 0; c0 < 256; c0 += 64) {
        for (int idx = tid; idx < 64*112; idx += 256) {
            int c = idx / 112, w = idx % 112;
            t[c][w] = g_combined[((size_t)(b*256 + c0 + c))*HW + h*WW + w];
        }
        __syncthreads();
        size_t dbase = (((size_t)b*114 + h + 1)*114 + 1)*256 + c0;
        for (int idx = tid; idx < 112*64; idx += 256) {
            int w = idx >> 6, c = idx & 63;
            float v = t[c][w];
            __nv_bfloat16 hi = __float2bfloat16(v);
            float r = v - __bfloat162float(hi);
            g_bhi[dbase + (size_t)w*256 + c] = hi;
            g_blo[dbase + (size_t)w*256 + c] = __float2bfloat16(r);
        }
        __syncthreads();
    }
}

// ============================================================
// 6) downsample via legacy mma.sync bf16 3-term split implicit GEMM
//    CTA: 128 co x 128 px; 8 warps, warp tile 64x32
//    smem: Ahi/Alo/Bhi/Blo each 128 rows x 40 bf16 (stride pad)
// ============================================================
#define DS_SMEM (4*128*40*2)     // 40960 B
__global__ void __launch_bounds__(256, 2) ds_mma_kernel(
    const float* __restrict__ dsb,
    const float* __restrict__ bn_g, const float* __restrict__ bn_b,
    const float* __restrict__ bn_m, const float* __restrict__ bn_v,
    float* __restrict__ out) {
    extern __shared__ __align__(16) uint32_t smw[];   // word view, 10240 words
    // word offsets: Ahi 0, Alo 2560, Bhi 5120, Blo 7680 (row stride 20 words)
    int tid  = threadIdx.x;
    int lane = tid & 31, w = tid >> 5;
    int wm = w & 1, wn = w >> 1;
    int g  = lane >> 2, tig = lane & 3;
    int coB = blockIdx.x * 128;
    int p0  = blockIdx.y * 128;

    int srow = tid & 127;
    bool isHi = tid < 128;
    const __nv_bfloat16* wsrc = isHi ? g_whi : g_wlo;
    const __nv_bfloat16* bsrc = isHi ? g_bhi : g_blo;
    {   // placement of this thread's staged rows
    }
    int pg = p0 + srow;
    int bimg = pg / OHW, lpx = pg % OHW;
    int ohh = lpx / OW, oww = lpx % OW;
    size_t rowbase = ((size_t)(bimg*114 + 2*ohh)*114 + 2*oww)*256;
    uint32_t aoff = (isHi ? 0u : 2560u) + (uint32_t)srow*20;
    uint32_t boff = (isHi ? 5120u : 7680u) + (uint32_t)srow*20;

    float acc[4][4][4];
    #pragma unroll
    for (int i = 0; i < 4; i++)
        #pragma unroll
        for (int j = 0; j < 4; j++)
            #pragma unroll
            for (int e = 0; e < 4; e++) acc[i][j][e] = 0.f;

    for (int st = 0; st < 72; st++) {
        int tap = st >> 3, cc = st & 7;
        int khw = (tap/3)*114 + (tap%3);
        // gmem loads (64B each), issued before barrier to hide latency
        const float4* ap = (const float4*)(wsrc +
            ((size_t)(tap*OUTC + coB + srow))*256 + cc*32);
        float4 ra0 = ap[0], ra1 = ap[1], ra2 = ap[2], ra3 = ap[3];
        const float4* bp = (const float4*)(bsrc + rowbase + (size_t)khw*256 + cc*32);
        float4 rb0 = bp[0], rb1 = bp[1], rb2 = bp[2], rb3 = bp[3];
        __syncthreads();          // everyone done computing previous stage
        {
            float4* ad = (float4*)(smw + aoff);
            ad[0] = ra0; ad[1] = ra1; ad[2] = ra2; ad[3] = ra3;
            float4* bd = (float4*)(smw + boff);
            bd[0] = rb0; bd[1] = rb1; bd[2] = rb2; bd[3] = rb3;
        }
        __syncthreads();
        #pragma unroll
        for (int s = 0; s < 2; s++) {
            int ko = s*8;
            uint32_t ahi[4][4], alo[4][4];
            #pragma unroll
            for (int i = 0; i < 4; i++) {
                int r0 = (wm*64 + i*16 + g)*20 + ko + tig;
                int r1 = r0 + 8*20;
                ahi[i][0] = smw[r0];        ahi[i][1] = smw[r1];
                ahi[i][2] = smw[r0+4];      ahi[i][3] = smw[r1+4];
                alo[i][0] = smw[2560+r0];   alo[i][1] = smw[2560+r1];
                alo[i][2] = smw[2560+r0+4]; alo[i][3] = smw[2560+r1+4];
            }
            #pragma unroll
            for (int j = 0; j < 4; j++) {
                int rbw = (wn*32 + j*8 + g)*20 + ko + tig;
                uint32_t bh0 = smw[5120+rbw], bh1 = smw[5120+rbw+4];
                uint32_t bl0 = smw[7680+rbw], bl1 = smw[7680+rbw+4];
                #pragma unroll
                for (int i = 0; i < 4; i++) {
                    mma_bf16(acc[i][j], ahi[i], bh0, bh1);   // hi*hi
                    mma_bf16(acc[i][j], ahi[i], bl0, bl1);   // hi*lo
                    mma_bf16(acc[i][j], alo[i], bh0, bh1);   // lo*hi
                }
            }
        }
    }

    // epilogue: BN + ReLU, scatter to NCHW out
    #pragma unroll
    for (int i = 0; i < 4; i++) {
        int coA = coB + wm*64 + i*16 + g;
        int coC = coA + 8;
        float invA = bn_g[coA] * rsqrtf(bn_v[coA] + EPSF);
        float shA  = bn_b[coA] - bn_m[coA]*invA + dsb[coA]*invA;
        float invC = bn_g[coC] * rsqrtf(bn_v[coC] + EPSF);
        float shC  = bn_b[coC] - bn_m[coC]*invC + dsb[coC]*invC;
        #pragma unroll
        for (int j = 0; j < 4; j++) {
            int n0 = p0 + wn*32 + j*8 + 2*tig;
            #pragma unroll
            for (int e = 0; e < 2; e++) {
                int pgx = n0 + e;
                int b = pgx / OHW, l = pgx % OHW;
                out[((size_t)(b*OUTC + coA))*OHW + l] =
                    fmaxf(fmaf(acc[i][j][e], invA, shA), 0.f);
                out[((size_t)(b*OUTC + coC))*OHW + l] =
                    fmaxf(fmaf(acc[i][j][2+e], invC, shC), 0.f);
            }
        }
    }
}

// ============================================================
extern "C" void kernel_launch(void* const* d_in, const int* in_sizes, int n_in,
                              void* d_out, int out_size) {
    const float* x     = (const float*)d_in[0];
    const float* Wkg   = (const float*)d_in[1];
    const float* gdw_w = (const float*)d_in[2];
    const float* gdw_b = (const float*)d_in[3];
    const float* gpw_w = (const float*)d_in[4];
    const float* gpw_b = (const float*)d_in[5];
    const float* bn1_g = (const float*)d_in[6];
    const float* bn1_b = (const float*)d_in[7];
    const float* bn1_m = (const float*)d_in[8];
    const float* bn1_v = (const float*)d_in[9];
    const float* ds_w  = (const float*)d_in[10];
    const float* ds_b  = (const float*)d_in[11];
    const float* bn2_g = (const float*)d_in[12];
    const float* bn2_b = (const float*)d_in[13];
    const float* bn2_m = (const float*)d_in[14];
    const float* bn2_v = (const float*)d_in[15];
    float* out = (float*)d_out;

    const int smem1 = (HH+2)*(WW+2)*sizeof(float);
    const int smem2 = (HH+4)*(WW+4)*sizeof(float);
    cudaFuncSetAttribute(dw_kernel<1>, cudaFuncAttributeMaxDynamicSharedMemorySize, smem1);
    cudaFuncSetAttribute(dw_kernel<2>, cudaFuncAttributeMaxDynamicSharedMemorySize, smem2);
    cudaFuncSetAttribute(ds_mma_kernel, cudaFuncAttributeMaxDynamicSharedMemorySize, DS_SMEM);

    float* t_ptr;    cudaGetSymbolAddress((void**)&t_ptr, g_t);
    float* comb_ptr; cudaGetSymbolAddress((void**)&comb_ptr, g_combined);

    repack_kernel<<<OUTC, 256>>>(ds_w);
    border_kernel<<<BB, 256>>>();
    pool_kernel<<<BB*MID, 256>>>(x);
    gen_kernel<<<dim3(BB, 9), 128>>>(Wkg);
    dw_kernel<1><<<BB*MID, 256, smem1>>>(x, 0, nullptr, nullptr, comb_ptr, 2*MID);
    dw_kernel<2><<<BB*MID, 256, smem2>>>(x, MID, gdw_w, gdw_b, t_ptr, MID);
    pw_kernel<<<dim3(HW/128, BB), 256>>>(gpw_w, gpw_b, bn1_g, bn1_b, bn1_m, bn1_v);
    transpose_kernel<<<dim3(HH, BB), 256>>>();
    ds_mma_kernel<<<dim3(4, (BB*OHW)/128), 256, DS_SMEM>>>(
        ds_b, bn2_g, bn2_b, bn2_m, bn2_v, out);
}

// round 7
// speedup vs baseline: 3.0948x; 1.4488x over previous
#include <cuda_runtime.h>
#include <cuda_fp16.h>
#include <cstddef>
#include <cstdint>

#define BB   16
#define MID  128
#define OUTC 512
#define HH   112
#define WW   112
#define HW   (HH*WW)      // 12544
#define OH   56
#define OW   56
#define OHW  (OH*OW)      // 3136
#define EPSF 1e-5f

// ---- packed f32x2 helpers ----
#define FMA2(acc, a, b) \
    asm("fma.rn.f32x2 %0, %1, %2, %0;" : "+l"(acc) : "l"(a), "l"(b))
#define PACK2(out, lo, hi) \
    asm("mov.b64 %0, {%1, %2};" : "=l"(out) : "r"(lo), "r"(hi))
#define UNPACK2(lo, hi, v) \
    asm("mov.b64 {%0, %1}, %2;" : "=r"(lo), "=r"(hi) : "l"(v))

// ---- legacy tensor-core mma fp16 (baseline PTX, works on sm_103 non-'a') ----
__device__ __forceinline__ void mma_f16(float* c, const uint32_t* a,
                                        uint32_t b0, uint32_t b1) {
    asm volatile(
        "mma.sync.aligned.m16n8k16.row.col.f32.f16.f16.f32 "
        "{%0,%1,%2,%3}, {%4,%5,%6,%7}, {%8,%9}, {%0,%1,%2,%3};"
        : "+f"(c[0]), "+f"(c[1]), "+f"(c[2]), "+f"(c[3])
        : "r"(a[0]), "r"(a[1]), "r"(a[2]), "r"(a[3]), "r"(b0), "r"(b1));
}

// ---- scratch (static device globals; no allocation) ----
__device__ float g_pooled[BB*MID];
__device__ float g_gen[BB*MID*9];
__device__ float g_t[(size_t)BB*MID*HW];
__device__ float g_combined[(size_t)BB*2*MID*HW];        // NCHW fp32
__device__ __half g_bhi[(size_t)BB*114*114*256];         // padded NHWC fp16 hi
__device__ __half g_blo[(size_t)BB*114*114*256];         // padded NHWC fp16 lo
__device__ __half g_wh[(size_t)9*OUTC*256];              // [tap][co][cin] fp16 hi

// ============================================================
// 1) global average pool
// ============================================================
__global__ void pool_kernel(const float* __restrict__ x) {
    int bc = blockIdx.x;
    int b = bc / MID, c = bc % MID;
    const float4* p = (const float4*)(x + ((size_t)(b*2*MID + c))*HW);
    float s = 0.f;
    for (int i = threadIdx.x; i < HW/4; i += 256) {
        float4 v = p[i];
        s += v.x + v.y + v.z + v.w;
    }
    __shared__ float red[256];
    red[threadIdx.x] = s;
    __syncthreads();
    for (int o = 128; o > 0; o >>= 1) {
        if (threadIdx.x < o) red[threadIdx.x] += red[threadIdx.x + o];
        __syncthreads();
    }
    if (threadIdx.x == 0) g_pooled[bc] = red[0] * (1.f/(float)HW);
}

// ============================================================
// 2) kernel-gen
// ============================================================
__global__ void gen_kernel(const float* __restrict__ Wkg) {
    int b = blockIdx.x;
    int o = blockIdx.y * 128 + threadIdx.x;
    __shared__ float ps[MID];
    ps[threadIdx.x] = g_pooled[b*MID + threadIdx.x];
    __syncthreads();
    const float4* wr = (const float4*)(Wkg + (size_t)o*MID);
    float s = 0.f;
    #pragma unroll
    for (int i = 0; i < MID/4; i++) {
        float4 w4 = wr[i];
        s += w4.x*ps[4*i] + w4.y*ps[4*i+1] + w4.z*ps[4*i+2] + w4.w*ps[4*i+3];
    }
    g_gen[b*MID*9 + o] = fmaxf(s, 0.f);
}

// ============================================================
// 3) depthwise 3x3 (dil 1 or 2)
// ============================================================
template<int DIL>
__global__ void dw_kernel(const float* __restrict__ x, int in_chan_off,
                          const float* __restrict__ kper,
                          const float* __restrict__ bias,
                          float* __restrict__ outbuf, int out_nchan) {
    constexpr int P  = DIL;
    constexpr int W2 = WW + 2*P;
    constexpr int H2 = HH + 2*P;
    extern __shared__ float sm[];
    int bc = blockIdx.x;
    int b = bc / MID, c = bc % MID;
    const float* in = x + ((size_t)(b*2*MID) + in_chan_off + c)*HW;

    for (int i = threadIdx.x; i < H2*W2; i += 256) sm[i] = 0.f;
    __syncthreads();
    for (int i = threadIdx.x; i < HW; i += 256) {
        int h = i / WW, w = i % WW;
        sm[(h+P)*W2 + w + P] = in[i];
    }
    __syncthreads();

    float k[9];
    const float* kp = kper ? (kper + c*9) : (g_gen + (b*MID + c)*9);
    #pragma unroll
    for (int t = 0; t < 9; t++) k[t] = kp[t];
    float bv = bias ? bias[c] : 0.f;

    float* out = outbuf + ((size_t)b*out_nchan + c)*HW;
    for (int i = threadIdx.x; i < HW; i += 256) {
        int h = i / WW, w = i % WW;
        const float* base = sm + h*W2 + w;
        float s = bv;
        #pragma unroll
        for (int kh = 0; kh < 3; kh++)
            #pragma unroll
            for (int kw = 0; kw < 3; kw++)
                s = fmaf(base[kh*DIL*W2 + kw*DIL], k[kh*3+kw], s);
        out[i] = s;
    }
}

// ============================================================
// 4) 1x1 conv + bias + BN + ReLU (f32x2)
// ============================================================
__global__ void pw_kernel(const float* __restrict__ wpw, const float* __restrict__ bpw,
                          const float* __restrict__ bn_g, const float* __restrict__ bn_b,
                          const float* __restrict__ bn_m, const float* __restrict__ bn_v) {
    __shared__ __align__(16) float wS[16*132];
    __shared__ __align__(16) float tS[16*132];
    int b  = blockIdx.y;
    int p0 = blockIdx.x * 128;
    int tid = threadIdx.x;
    int ty = tid >> 4, tx = tid & 15;
    unsigned long long acc[8][4];
    #pragma unroll
    for (int i = 0; i < 8; i++)
        #pragma unroll
        for (int j = 0; j < 4; j++) acc[i][j] = 0ULL;
    const float* tbase = g_t + (size_t)b*MID*HW;

    for (int kc = 0; kc < 8; kc++) {
        __syncthreads();
        for (int idx = tid; idx < 2048; idx += 256) {
            int k = idx & 15, co = idx >> 4;
            wS[k*132 + co] = wpw[co*MID + kc*16 + k];
        }
        for (int idx = tid; idx < 2048; idx += 256) {
            int k = idx >> 7, px = idx & 127;
            tS[k*132 + px] = tbase[(kc*16 + k)*HW + p0 + px];
        }
        __syncthreads();
        #pragma unroll
        for (int k = 0; k < 16; k++) {
            float4 a0 = *(const float4*)&wS[k*132 + ty*8];
            float4 a1 = *(const float4*)&wS[k*132 + ty*8 + 4];
            float a[8] = {a0.x,a0.y,a0.z,a0.w,a1.x,a1.y,a1.z,a1.w};
            unsigned long long ad[8];
            #pragma unroll
            for (int i = 0; i < 8; i++) {
                unsigned int ab = __float_as_uint(a[i]);
                PACK2(ad[i], ab, ab);
            }
            const ulonglong2* bp = (const ulonglong2*)&tS[k*132 + tx*8];
            ulonglong2 b01 = bp[0];
            ulonglong2 b23 = bp[1];
            unsigned long long bv[4] = {b01.x, b01.y, b23.x, b23.y};
            #pragma unroll
            for (int i = 0; i < 8; i++)
                #pragma unroll
                for (int j = 0; j < 4; j++)
                    FMA2(acc[i][j], ad[i], bv[j]);
        }
    }
    #pragma unroll
    for (int i = 0; i < 8; i++) {
        int co = ty*8 + i;
        float inv = bn_g[co] * rsqrtf(bn_v[co] + EPSF);
        float sh  = bn_b[co] - bn_m[co]*inv + bpw[co]*inv;
        float* o = g_combined + ((size_t)(b*2*MID) + MID + co)*HW + p0 + tx*8;
        #pragma unroll
        for (int j = 0; j < 4; j++) {
            unsigned int lo, hi;
            UNPACK2(lo, hi, acc[i][j]);
            o[2*j]   = fmaxf(fmaf(__uint_as_float(lo), inv, sh), 0.f);
            o[2*j+1] = fmaxf(fmaf(__uint_as_float(hi), inv, sh), 0.f);
        }
    }
}

// ============================================================
// 5a) weight repack: dsw[co][cin][tap] -> [tap][co][cin] fp16 hi
// ============================================================
__global__ void repack_kernel(const float* __restrict__ dsw) {
    int co = blockIdx.x, cin = threadIdx.x;
    const float* src = dsw + ((size_t)co*256 + cin)*9;
    #pragma unroll
    for (int t = 0; t < 9; t++)
        g_wh[((size_t)t*OUTC + co)*256 + cin] = __float2half_rn(src[t]);
}

// ============================================================
// 5b) border zero for padded NHWC fp16 buffers
// ============================================================
__global__ void border_kernel() {
    size_t base = (size_t)blockIdx.x * 114*114*256;
    int tid = threadIdx.x;
    __half z = __float2half_rn(0.f);
    for (int idx = tid; idx < 114*256; idx += 256) {
        g_bhi[base + idx] = z;  g_blo[base + idx] = z;
        g_bhi[base + (size_t)113*114*256 + idx] = z;
        g_blo[base + (size_t)113*114*256 + idx] = z;
    }
    for (int idx = tid; idx < 112*256; idx += 256) {
        int h = idx >> 8, c = idx & 255;
        size_t i0 = base + ((size_t)(h+1)*114)*256 + c;
        size_t i1 = base + ((size_t)(h+1)*114 + 113)*256 + c;
        g_bhi[i0] = z; g_blo[i0] = z;
        g_bhi[i1] = z; g_blo[i1] = z;
    }
}

// ============================================================
// 5c) transpose NCHW fp32 -> padded NHWC fp16 hi/lo
// ============================================================
__global__ void transpose_kernel() {
    __shared__ float t[64][113];
    int h = blockIdx.x, b = blockIdx.y;
    int tid = threadIdx.x;
    for (int c0 = 0; c0 < 256; c0 += 64) {
        for (int idx = tid; idx < 64*112; idx += 256) {
            int c = idx / 112, w = idx % 112;
            t[c][w] = g_combined[((size_t)(b*256 + c0 + c))*HW + h*WW + w];
        }
        __syncthreads();
        size_t dbase = (((size_t)b*114 + h + 1)*114 + 1)*256 + c0;
        for (int idx = tid; idx < 112*64; idx += 256) {
            int w = idx >> 6, c = idx & 63;
            float v = t[c][w];
            __half hi = __float2half_rn(v);
            float r = v - __half2float(hi);
            g_bhi[dbase + (size_t)w*256 + c] = hi;
            g_blo[dbase + (size_t)w*256 + c] = __float2half_rn(r);
        }
        __syncthreads();
    }
}

// ============================================================
// 6) downsample: mma.sync fp16 2-term implicit GEMM, double-buffered
//    CTA: 128 co x 128 px; 8 warps, warp tile 64x32
//    smem per stage: Ahi / Bhi / Blo, 128 rows x 20 words each
// ============================================================
#define STG_W   7680                     // words per stage (3 * 2560)
#define DS_SMEM (2*STG_W*4)              // 61440 B
__global__ void __launch_bounds__(256, 2) ds_mma_kernel(
    const float* __restrict__ dsb,
    const float* __restrict__ bn_g, const float* __restrict__ bn_b,
    const float* __restrict__ bn_m, const float* __restrict__ bn_v,
    float* __restrict__ out) {
    extern __shared__ __align__(16) uint32_t smw[];   // 2*7680 words
    int tid  = threadIdx.x;
    int lane = tid & 31, w = tid >> 5;
    int wm = w & 1, wn = w >> 1;
    int g  = lane >> 2, tig = lane & 3;
    int coB = blockIdx.x * 128;
    int p0  = blockIdx.y * 128;

    // staging: every thread loads 32B half-rows of Ahi, Bhi, Blo for row r
    int r  = tid >> 1, hf = tid & 1;
    size_t aBase;
    {
        aBase = (size_t)(coB + r)*256 + hf*16;
    }
    size_t bBase;
    {
        int pg = p0 + r;
        int bimg = pg / OHW, lpx = pg % OHW;
        int ohh = lpx / OW, oww = lpx % OW;
        bBase = ((size_t)(bimg*114 + 2*ohh)*114 + 2*oww)*256 + hf*16;
    }
    uint32_t sA = (uint32_t)(r*20 + hf*8);

    float acc[4][4][4];
    #pragma unroll
    for (int i = 0; i < 4; i++)
        #pragma unroll
        for (int j = 0; j < 4; j++)
            #pragma unroll
            for (int e = 0; e < 4; e++) acc[i][j][e] = 0.f;

    float4 rA0, rA1, rH0, rH1, rL0, rL1;
    // prefetch stage 0
    {
        const float4* ap = (const float4*)(g_wh + aBase);
        rA0 = ap[0]; rA1 = ap[1];
        const float4* hp = (const float4*)(g_bhi + bBase);
        rH0 = hp[0]; rH1 = hp[1];
        const float4* lp = (const float4*)(g_blo + bBase);
        rL0 = lp[0]; rL1 = lp[1];
    }

    for (int st = 0; st < 72; st++) {
        uint32_t sb = (uint32_t)(st & 1) * STG_W;
        {   // store prefetched regs into this stage's buffer
            float4* ad = (float4*)(smw + sb + sA);
            ad[0] = rA0; ad[1] = rA1;
            float4* hd = (float4*)(smw + sb + 2560 + sA);
            hd[0] = rH0; hd[1] = rH1;
            float4* ld = (float4*)(smw + sb + 5120 + sA);
            ld[0] = rL0; ld[1] = rL1;
        }
        __syncthreads();
        if (st < 71) {     // prefetch next stage (in flight during compute)
            int sn = st + 1;
            int tap = sn >> 3, cc = sn & 7;
            size_t ao = aBase + (size_t)tap*(OUTC*256) + cc*32;
            size_t bo = bBase + (size_t)((tap/3)*114 + tap%3)*256 + cc*32;
            const float4* ap = (const float4*)(g_wh + ao);
            rA0 = ap[0]; rA1 = ap[1];
            const float4* hp = (const float4*)(g_bhi + bo);
            rH0 = hp[0]; rH1 = hp[1];
            const float4* lp = (const float4*)(g_blo + bo);
            rL0 = lp[0]; rL1 = lp[1];
        }
        // compute from buffer sb
        #pragma unroll
        for (int s2 = 0; s2 < 2; s2++) {
            int ko = s2*8;
            uint32_t a[4][4];
            #pragma unroll
            for (int i = 0; i < 4; i++) {
                int r0 = (wm*64 + i*16 + g)*20 + ko + tig;
                int r1 = r0 + 160;
                a[i][0] = smw[sb+r0];   a[i][1] = smw[sb+r1];
                a[i][2] = smw[sb+r0+4]; a[i][3] = smw[sb+r1+4];
            }
            #pragma unroll
            for (int j = 0; j < 4; j++) {
                int rbw = (wn*32 + j*8 + g)*20 + ko + tig;
                uint32_t bh0 = smw[sb+2560+rbw], bh1 = smw[sb+2560+rbw+4];
                uint32_t bl0 = smw[sb+5120+rbw], bl1 = smw[sb+5120+rbw+4];
                #pragma unroll
                for (int i = 0; i < 4; i++) {
                    mma_f16(acc[i][j], a[i], bh0, bh1);   // hi * hi
                    mma_f16(acc[i][j], a[i], bl0, bl1);   // hi * lo
                }
            }
        }
    }

    // epilogue: BN + ReLU, scatter to NCHW out
    #pragma unroll
    for (int i = 0; i < 4; i++) {
        int coA = coB + wm*64 + i*16 + g;
        int coC = coA + 8;
        float invA = bn_g[coA] * rsqrtf(bn_v[coA] + EPSF);
        float shA  = bn_b[coA] - bn_m[coA]*invA + dsb[coA]*invA;
        float invC = bn_g[coC] * rsqrtf(bn_v[coC] + EPSF);
        float shC  = bn_b[coC] - bn_m[coC]*invC + dsb[coC]*invC;
        #pragma unroll
        for (int j = 0; j < 4; j++) {
            int n0 = p0 + wn*32 + j*8 + 2*tig;
            #pragma unroll
            for (int e = 0; e < 2; e++) {
                int pgx = n0 + e;
                int b = pgx / OHW, l = pgx % OHW;
                out[((size_t)(b*OUTC + coA))*OHW + l] =
                    fmaxf(fmaf(acc[i][j][e], invA, shA), 0.f);
                out[((size_t)(b*OUTC + coC))*OHW + l] =
                    fmaxf(fmaf(acc[i][j][2+e], invC, shC), 0.f);
            }
        }
    }
}

// ============================================================
extern "C" void kernel_launch(void* const* d_in, const int* in_sizes, int n_in,
                              void* d_out, int out_size) {
    const float* x     = (const float*)d_in[0];
    const float* Wkg   = (const float*)d_in[1];
    const float* gdw_w = (const float*)d_in[2];
    const float* gdw_b = (const float*)d_in[3];
    const float* gpw_w = (const float*)d_in[4];
    const float* gpw_b = (const float*)d_in[5];
    const float* bn1_g = (const float*)d_in[6];
    const float* bn1_b = (const float*)d_in[7];
    const float* bn1_m = (const float*)d_in[8];
    const float* bn1_v = (const float*)d_in[9];
    const float* ds_w  = (const float*)d_in[10];
    const float* ds_b  = (const float*)d_in[11];
    const float* bn2_g = (const float*)d_in[12];
    const float* bn2_b = (const float*)d_in[13];
    const float* bn2_m = (const float*)d_in[14];
    const float* bn2_v = (const float*)d_in[15];
    float* out = (float*)d_out;

    const int smem1 = (HH+2)*(WW+2)*sizeof(float);
    const int smem2 = (HH+4)*(WW+4)*sizeof(float);
    cudaFuncSetAttribute(dw_kernel<1>, cudaFuncAttributeMaxDynamicSharedMemorySize, smem1);
    cudaFuncSetAttribute(dw_kernel<2>, cudaFuncAttributeMaxDynamicSharedMemorySize, smem2);
    cudaFuncSetAttribute(ds_mma_kernel, cudaFuncAttributeMaxDynamicSharedMemorySize, DS_SMEM);

    float* t_ptr;    cudaGetSymbolAddress((void**)&t_ptr, g_t);
    float* comb_ptr; cudaGetSymbolAddress((void**)&comb_ptr, g_combined);

    repack_kernel<<<OUTC, 256>>>(ds_w);
    border_kernel<<<BB, 256>>>();
    pool_kernel<<<BB*MID, 256>>>(x);
    gen_kernel<<<dim3(BB, 9), 128>>>(Wkg);
    dw_kernel<1><<<BB*MID, 256, smem1>>>(x, 0, nullptr, nullptr, comb_ptr, 2*MID);
    dw_kernel<2><<<BB*MID, 256, smem2>>>(x, MID, gdw_w, gdw_b, t_ptr, MID);
    pw_kernel<<<dim3(HW/128, BB), 256>>>(gpw_w, gpw_b, bn1_g, bn1_b, bn1_m, bn1_v);
    transpose_kernel<<<dim3(HH, BB), 256>>>();
    ds_mma_kernel<<<dim3(4, (BB*OHW)/128), 256, DS_SMEM>>>(
        ds_b, bn2_g, bn2_b, bn2_m, bn2_v, out);
}